// round 1
// baseline (speedup 1.0000x reference)
#include <cuda_runtime.h>

#define TCOLS 4096
#define BROWS 4096
#define NTHREADS 256
#define NWARPS (NTHREADS / 32)

// Per-row partial squared errors (deterministic, no atomics).
__device__ float g_partials[BROWS];

__device__ __forceinline__ float warp_sum(float v) {
    #pragma unroll
    for (int o = 16; o; o >>= 1) v += __shfl_xor_sync(0xffffffffu, v, o);
    return v;
}

// Reduce N per-thread values across the block; result broadcast into vals[].
template <int N>
__device__ __forceinline__ void block_reduce(float* vals, float* red, int tid) {
    const int lane = tid & 31;
    const int wid  = tid >> 5;
    #pragma unroll
    for (int k = 0; k < N; k++) {
        float v = warp_sum(vals[k]);
        if (lane == 0) red[k * NWARPS + wid] = v;
    }
    __syncthreads();
    #pragma unroll
    for (int k = 0; k < N; k++) {
        float s = 0.f;
        #pragma unroll
        for (int w = 0; w < NWARPS; w++) s += red[k * NWARPS + w];
        vals[k] = s;
    }
    __syncthreads();   // red[] free for reuse
}

__global__ __launch_bounds__(NTHREADS)
void pv_row_kernel(const float* __restrict__ preds,
                   const float* __restrict__ labels) {
    __shared__ float sp[TCOLS];
    __shared__ float sl[TCOLS];
    __shared__ float red[16 * NWARPS];

    const int row = blockIdx.x;
    const int tid = threadIdx.x;

    // Coalesced float4 loads of both rows into SMEM.
    const float4* gp = (const float4*)(preds  + (size_t)row * TCOLS);
    const float4* gl = (const float4*)(labels + (size_t)row * TCOLS);
    float4* s4p = (float4*)sp;
    float4* s4l = (float4*)sl;
    #pragma unroll
    for (int k = 0; k < TCOLS / 4 / NTHREADS; k++) {
        int i = tid + k * NTHREADS;
        s4p[i] = gp[i];
        s4l[i] = gl[i];
    }
    __syncthreads();

    // Pass 1: peak/valley sums & counts for both arrays.
    // acc: 0 psum_p 1 pcnt_p 2 vsum_p 3 vcnt_p 4 psum_l 5 pcnt_l 6 vsum_l 7 vcnt_l
    float acc[8];
    #pragma unroll
    for (int k = 0; k < 8; k++) acc[k] = 0.f;

    for (int i = tid; i < TCOLS - 2; i += NTHREADS) {
        {
            float a = sp[i], b = sp[i + 1], c = sp[i + 2];
            float dl = b - a, dr = c - b;
            bool pk = (dl > 0.f) & (dr < 0.f);
            bool vy = (dl < 0.f) & (dr > 0.f);
            if (pk) { acc[0] += b; acc[1] += 1.f; }
            if (vy) { acc[2] += b; acc[3] += 1.f; }
        }
        {
            float a = sl[i], b = sl[i + 1], c = sl[i + 2];
            float dl = b - a, dr = c - b;
            bool pk = (dl > 0.f) & (dr < 0.f);
            bool vy = (dl < 0.f) & (dr > 0.f);
            if (pk) { acc[4] += b; acc[5] += 1.f; }
            if (vy) { acc[6] += b; acc[7] += 1.f; }
        }
    }
    block_reduce<8>(acc, red, tid);

    const float pmean_p = acc[0] / acc[1];
    const float vmean_p = acc[2] / acc[3];
    const float pmean_l = acc[4] / acc[5];
    const float vmean_l = acc[6] / acc[7];

    // Pass 2: thresholded masked means.
    // s: 0 sbp_sum_p 1 sbp_cnt_p 2 dbp_sum_p 3 dbp_cnt_p 4..7 same for labels
    float s[8];
    #pragma unroll
    for (int k = 0; k < 8; k++) s[k] = 0.f;

    for (int i = tid; i < TCOLS - 2; i += NTHREADS) {
        {
            float a = sp[i], b = sp[i + 1], c = sp[i + 2];
            float dl = b - a, dr = c - b;
            bool pk = (dl > 0.f) & (dr < 0.f);
            bool vy = (dl < 0.f) & (dr > 0.f);
            if (pk && b >= pmean_p) { s[0] += b; s[1] += 1.f; }
            if (vy && b <= vmean_p) { s[2] += b; s[3] += 1.f; }
        }
        {
            float a = sl[i], b = sl[i + 1], c = sl[i + 2];
            float dl = b - a, dr = c - b;
            bool pk = (dl > 0.f) & (dr < 0.f);
            bool vy = (dl < 0.f) & (dr > 0.f);
            if (pk && b >= pmean_l) { s[4] += b; s[5] += 1.f; }
            if (vy && b <= vmean_l) { s[6] += b; s[7] += 1.f; }
        }
    }
    block_reduce<8>(s, red, tid);

    if (tid == 0) {
        float sbp_p = s[0] / s[1];
        float dbp_p = s[2] / s[3];
        float sbp_l = s[4] / s[5];
        float dbp_l = s[6] / s[7];
        float d0 = sbp_p - sbp_l;
        float d1 = dbp_p - dbp_l;
        g_partials[row] = d0 * d0 + d1 * d1;
    }
}

__global__ __launch_bounds__(1024)
void pv_final_kernel(float* __restrict__ out) {
    __shared__ float red[32];
    const int tid = threadIdx.x;
    float v = 0.f;
    #pragma unroll
    for (int k = 0; k < BROWS / 1024; k++) v += g_partials[tid + k * 1024];
    v = warp_sum(v);
    if ((tid & 31) == 0) red[tid >> 5] = v;
    __syncthreads();
    if (tid < 32) {
        float s = (tid < 32) ? red[tid] : 0.f;
        // 32 warps per 1024 threads
        s = warp_sum(s);
        if (tid == 0) out[0] = s / (float)(BROWS * 2);
    }
}

extern "C" void kernel_launch(void* const* d_in, const int* in_sizes, int n_in,
                              void* d_out, int out_size) {
    const float* preds  = (const float*)d_in[0];
    const float* labels = (const float*)d_in[1];
    float* out = (float*)d_out;
    pv_row_kernel<<<BROWS, NTHREADS>>>(preds, labels);
    pv_final_kernel<<<1, 1024>>>(out);
}

// round 2
// speedup vs baseline: 1.0666x; 1.0666x over previous
#include <cuda_runtime.h>

#define TCOLS 4096
#define BROWS 4096
#define NT 256
#define NW (NT / 32)
#define EPT 16   // centers per thread (NT * EPT == TCOLS)

__device__ float    g_partials[BROWS];
__device__ unsigned g_done;   // zero-init; reset to 0 by last block each launch

__device__ __forceinline__ float warp_sum(float v) {
    #pragma unroll
    for (int o = 16; o; o >>= 1) v += __shfl_xor_sync(0xffffffffu, v, o);
    return v;
}

template <int N>
__device__ __forceinline__ void block_reduce(float* vals, float* red, int tid) {
    const int lane = tid & 31;
    const int wid  = tid >> 5;
    #pragma unroll
    for (int k = 0; k < N; k++) {
        float v = warp_sum(vals[k]);
        if (lane == 0) red[k * NW + wid] = v;
    }
    __syncthreads();
    #pragma unroll
    for (int k = 0; k < N; k++) {
        float s = 0.f;
        #pragma unroll
        for (int w = 0; w < NW; w++) s += red[k * NW + w];
        vals[k] = s;
    }
    __syncthreads();
}

__global__ __launch_bounds__(NT)
void pv_fused_kernel(const float* __restrict__ preds,
                     const float* __restrict__ labels,
                     float* __restrict__ out) {
    __shared__ float red[8 * NW];
    __shared__ bool  amLast;

    const int row  = blockIdx.x;
    const int tid  = threadIdx.x;
    const int base = tid * EPT;

    // ---- Load this thread's chunk of both rows into registers ----
    float vp[EPT + 2], vl[EPT + 2];
    {
        const float4* gp = (const float4*)(preds  + (size_t)row * TCOLS) + tid * (EPT / 4);
        const float4* gl = (const float4*)(labels + (size_t)row * TCOLS) + tid * (EPT / 4);
        #pragma unroll
        for (int q = 0; q < EPT / 4; q++) {
            float4 a = gp[q];
            vp[4 * q] = a.x; vp[4 * q + 1] = a.y; vp[4 * q + 2] = a.z; vp[4 * q + 3] = a.w;
            float4 b = gl[q];
            vl[4 * q] = b.x; vl[4 * q + 1] = b.y; vl[4 * q + 2] = b.z; vl[4 * q + 3] = b.w;
        }
        if (base + EPT + 1 < TCOLS) {
            float2 e = *(const float2*)(preds  + (size_t)row * TCOLS + base + EPT);
            float2 f = *(const float2*)(labels + (size_t)row * TCOLS + base + EPT);
            vp[EPT] = e.x; vp[EPT + 1] = e.y;
            vl[EPT] = f.x; vl[EPT + 1] = f.y;
        } else {
            vp[EPT] = 0.f; vp[EPT + 1] = 0.f;
            vl[EPT] = 0.f; vl[EPT + 1] = 0.f;
        }
    }

    // valid centers: c = base+1+k must satisfy c <= TCOLS-2  ->  k < limit
    const int limit = (TCOLS - 2) - base;

    // ---- Pass 1: peak/valley sums, counts, masks ----
    unsigned pkm_p = 0, vym_p = 0, pkm_l = 0, vym_l = 0;
    float acc[8];
    #pragma unroll
    for (int k = 0; k < 8; k++) acc[k] = 0.f;

    {
        float dlp = vp[1] - vp[0];
        float dll = vl[1] - vl[0];
        #pragma unroll
        for (int k = 0; k < EPT; k++) {
            const bool ok = (k < limit);
            float drp = vp[k + 2] - vp[k + 1];
            bool pk = (dlp > 0.f) & (drp < 0.f) & ok;
            bool vy = (dlp < 0.f) & (drp > 0.f) & ok;
            if (pk) { acc[0] += vp[k + 1]; acc[1] += 1.f; pkm_p |= 1u << k; }
            if (vy) { acc[2] += vp[k + 1]; acc[3] += 1.f; vym_p |= 1u << k; }
            dlp = drp;

            float drl = vl[k + 2] - vl[k + 1];
            pk = (dll > 0.f) & (drl < 0.f) & ok;
            vy = (dll < 0.f) & (drl > 0.f) & ok;
            if (pk) { acc[4] += vl[k + 1]; acc[5] += 1.f; pkm_l |= 1u << k; }
            if (vy) { acc[6] += vl[k + 1]; acc[7] += 1.f; vym_l |= 1u << k; }
            dll = drl;
        }
    }
    block_reduce<8>(acc, red, tid);

    const float pmean_p = acc[0] / acc[1];
    const float vmean_p = acc[2] / acc[3];
    const float pmean_l = acc[4] / acc[5];
    const float vmean_l = acc[6] / acc[7];

    // ---- Pass 2: thresholded masked means (register data, bitmask reuse) ----
    float s[8];
    #pragma unroll
    for (int k = 0; k < 8; k++) s[k] = 0.f;

    #pragma unroll
    for (int k = 0; k < EPT; k++) {
        const float bp = vp[k + 1];
        if (((pkm_p >> k) & 1u) && bp >= pmean_p) { s[0] += bp; s[1] += 1.f; }
        if (((vym_p >> k) & 1u) && bp <= vmean_p) { s[2] += bp; s[3] += 1.f; }
        const float bl = vl[k + 1];
        if (((pkm_l >> k) & 1u) && bl >= pmean_l) { s[4] += bl; s[5] += 1.f; }
        if (((vym_l >> k) & 1u) && bl <= vmean_l) { s[6] += bl; s[7] += 1.f; }
    }
    block_reduce<8>(s, red, tid);

    if (tid == 0) {
        float sbp_p = s[0] / s[1];
        float dbp_p = s[2] / s[3];
        float sbp_l = s[4] / s[5];
        float dbp_l = s[6] / s[7];
        float d0 = sbp_p - sbp_l;
        float d1 = dbp_p - dbp_l;
        g_partials[row] = d0 * d0 + d1 * d1;
        __threadfence();
        unsigned c = atomicAdd(&g_done, 1u);
        amLast = (c == (unsigned)(gridDim.x - 1));
    }
    __syncthreads();

    // ---- Last block: reduce all per-row partials, write scalar, reset ----
    if (amLast) {
        float v = 0.f;
        #pragma unroll
        for (int q = 0; q < BROWS / NT; q++) v += g_partials[tid + q * NT];
        v = warp_sum(v);
        const int lane = tid & 31;
        const int wid  = tid >> 5;
        if (lane == 0) red[wid] = v;
        __syncthreads();
        if (tid == 0) {
            float t = 0.f;
            #pragma unroll
            for (int w = 0; w < NW; w++) t += red[w];
            out[0] = t / (float)(BROWS * 2);
            g_done = 0;   // ready for next graph replay
        }
    }
}

extern "C" void kernel_launch(void* const* d_in, const int* in_sizes, int n_in,
                              void* d_out, int out_size) {
    const float* preds  = (const float*)d_in[0];
    const float* labels = (const float*)d_in[1];
    pv_fused_kernel<<<BROWS, NT>>>(preds, labels, (float*)d_out);
}